// round 14
// baseline (speedup 1.0000x reference)
#include <cuda_runtime.h>
#include <cuda_bf16.h>
#include <mma.h>
#include <cstdint>

using namespace nvcuda;

#define N_NODES   100000
#define N_EDGES   1600000
#define D_FEAT    128
#define HIDDEN    128
#define N_CLASSES 10
#define NUM_GRAPHS 64
#define N_PAD     100096   // 782 * 128
#define NBLK      391      // ceil(N_NODES / 256)

typedef __nv_bfloat16 bf16;
typedef __nv_bfloat162 bf162;

#define LDT32 40           // padded bf16 row length for 32-col chunks (80 B)

// ---------------- scratch (no allocs allowed) ----------------
__device__ float g_h1 [(size_t)N_PAD * 128];
__device__ float g_h2 [(size_t)N_PAD * 128];
// hi/lo rows: [128 hi | 128 lo] bf16 per node (512 B)
__device__ bf16  g_xhl [(size_t)N_PAD * 256];
__device__ bf16  g_ahl [(size_t)N_PAD * 256];
__device__ bf16  g_h1hl[(size_t)N_PAD * 256];
__device__ bf16  g_h2hl[(size_t)N_PAD * 256];
// weights pre-split, chunk32-tiled: [3 layers][8 chunks][128 n][LDT32]
__device__ bf16  g_whi[3 * 8 * 128 * LDT32];
__device__ bf16  g_wlo[3 * 8 * 128 * LDT32];
__device__ float g_pooled[NUM_GRAPHS * HIDDEN];
__device__ int   g_deg [N_NODES];
__device__ int   g_off [N_NODES + 1];
__device__ int   g_cur [N_NODES];
__device__ int   g_srcs[N_EDGES];
__device__ int   g_blksum[NBLK];
__device__ int   g_blkoff[NBLK];

// ---------------- helpers ----------------
__device__ __forceinline__ uint32_t smem_u32(const void* p) {
    uint32_t a;
    asm("{ .reg .u64 t; cvta.to.shared.u64 t, %1; cvt.u32.u64 %0, t; }" : "=r"(a) : "l"(p));
    return a;
}
__device__ __forceinline__ void cp16(uint32_t dst, const void* src) {
    asm volatile("cp.async.cg.shared.global [%0], [%1], 16;" :: "r"(dst), "l"(src));
}
#define CP_COMMIT() asm volatile("cp.async.commit_group;" ::: "memory")
#define CP_WAIT1()  asm volatile("cp.async.wait_group 1;" ::: "memory")
#define CP_WAIT0()  asm volatile("cp.async.wait_group 0;" ::: "memory")

__device__ __forceinline__ void split4(float4 v, uint2& hi, uint2& lo) {
    bf162 h0, h1, l0, l1;
    h0.x = __float2bfloat16(v.x); h0.y = __float2bfloat16(v.y);
    h1.x = __float2bfloat16(v.z); h1.y = __float2bfloat16(v.w);
    l0.x = __float2bfloat16(v.x - __bfloat162float(h0.x));
    l0.y = __float2bfloat16(v.y - __bfloat162float(h0.y));
    l1.x = __float2bfloat16(v.z - __bfloat162float(h1.x));
    l1.y = __float2bfloat16(v.w - __bfloat162float(h1.y));
    hi.x = *reinterpret_cast<uint32_t*>(&h0); hi.y = *reinterpret_cast<uint32_t*>(&h1);
    lo.x = *reinterpret_cast<uint32_t*>(&l0); lo.y = *reinterpret_cast<uint32_t*>(&l1);
}

// ---------------- one-time conversions ----------------
__global__ void __launch_bounds__(256) cvt_x_kernel(
    const float* __restrict__ x, bf16* __restrict__ xhl)
{
    int t = blockIdx.x * blockDim.x + threadIdx.x;
    if (t >= N_NODES * 32) return;
    int node = t >> 5, j = (t & 31) * 4;
    float4 v = __ldg(reinterpret_cast<const float4*>(x + (size_t)node * 128 + j));
    uint2 hi, lo;
    split4(v, hi, lo);
    *reinterpret_cast<uint2*>(xhl + (size_t)node * 256 + j)       = hi;
    *reinterpret_cast<uint2*>(xhl + (size_t)node * 256 + 128 + j) = lo;
}

__global__ void __launch_bounds__(256) cvt_w_kernel(
    const float* __restrict__ W1l, const float* __restrict__ W1r,
    const float* __restrict__ W2l, const float* __restrict__ W2r,
    const float* __restrict__ W3l, const float* __restrict__ W3r,
    bf16* __restrict__ whi, bf16* __restrict__ wlo)
{
    int id = blockIdx.x * blockDim.x + threadIdx.x;   // 3*128*64 quads
    if (id >= 3 * 128 * 64) return;
    int l = id / (128 * 64);
    int n = (id / 64) % 128;
    int k = (id & 63) * 4;            // 0..252
    const float* Wl = (l == 0) ? W1l : (l == 1) ? W2l : W3l;
    const float* Wr = (l == 0) ? W1r : (l == 1) ? W2r : W3r;
    float4 v;
    if (k < 128) v = __ldg(reinterpret_cast<const float4*>(Wl + n * 128 + k));
    else         v = __ldg(reinterpret_cast<const float4*>(Wr + n * 128 + k - 128));
    uint2 hi, lo;
    split4(v, hi, lo);
    int c  = k >> 5;                  // chunk of 32
    int kk = k & 31;
    size_t dst = ((size_t)(l * 8 + c) * 128 + n) * LDT32 + kk;
    *reinterpret_cast<uint2*>(whi + dst) = hi;
    *reinterpret_cast<uint2*>(wlo + dst) = lo;
}

// ---------------- CSR build ----------------
__global__ void __launch_bounds__(256) zero_deg_kernel(int* __restrict__ deg)
{
    int i = blockIdx.x * blockDim.x + threadIdx.x;
    if (i < N_NODES) deg[i] = 0;
}
__global__ void __launch_bounds__(256) hist_kernel(
    const int* __restrict__ ei, int* __restrict__ deg)
{
    int e = blockIdx.x * blockDim.x + threadIdx.x;
    if (e >= N_EDGES) return;
    atomicAdd(deg + __ldg(ei + N_EDGES + e), 1);
}
__global__ void __launch_bounds__(256) partial_kernel(
    const int* __restrict__ deg, int* __restrict__ blksum)
{
    __shared__ int wsum[8];
    int i = blockIdx.x * 256 + threadIdx.x;
    int v = (i < N_NODES) ? deg[i] : 0;
#pragma unroll
    for (int d = 16; d > 0; d >>= 1) v += __shfl_down_sync(0xffffffffu, v, d);
    if ((threadIdx.x & 31) == 0) wsum[threadIdx.x >> 5] = v;
    __syncthreads();
    if (threadIdx.x < 8) {
        int s = wsum[threadIdx.x];
#pragma unroll
        for (int d = 4; d > 0; d >>= 1) s += __shfl_down_sync(0xffu, s, d);
        if (threadIdx.x == 0) blksum[blockIdx.x] = s;
    }
}
__global__ void __launch_bounds__(512) scan_blocks_kernel(
    const int* __restrict__ blksum, int* __restrict__ blkoff)
{
    __shared__ int sh[512];
    int t = threadIdx.x;
    sh[t] = (t < NBLK) ? blksum[t] : 0;
    __syncthreads();
#pragma unroll
    for (int d = 1; d < 512; d <<= 1) {
        int v = (t >= d) ? sh[t - d] : 0;
        __syncthreads();
        sh[t] += v;
        __syncthreads();
    }
    if (t < NBLK) blkoff[t] = sh[t] - blksum[t];
}
__global__ void __launch_bounds__(256) fill_off_kernel(
    const int* __restrict__ deg, const int* __restrict__ blkoff,
    int* __restrict__ off, int* __restrict__ cur)
{
    __shared__ int sh[256];
    int t = threadIdx.x;
    int i = blockIdx.x * 256 + t;
    int v = (i < N_NODES) ? deg[i] : 0;
    sh[t] = v;
    __syncthreads();
#pragma unroll
    for (int d = 1; d < 256; d <<= 1) {
        int u = (t >= d) ? sh[t - d] : 0;
        __syncthreads();
        sh[t] += u;
        __syncthreads();
    }
    if (i < N_NODES) {
        int excl = blkoff[blockIdx.x] + sh[t] - v;
        off[i] = excl;
        cur[i] = excl;
    }
    if (blockIdx.x == 0 && t == 0) off[N_NODES] = N_EDGES;
}
__global__ void __launch_bounds__(256) fill_kernel(
    const int* __restrict__ ei, int* __restrict__ cur, int* __restrict__ srcs)
{
    int e = blockIdx.x * blockDim.x + threadIdx.x;
    if (e >= N_EDGES) return;
    int src = __ldg(ei + e);
    int dst = __ldg(ei + N_EDGES + e);
    int pos = atomicAdd(cur + dst, 1);
    srcs[pos] = src;
}

// ---------------- gather aggregation: fp32 gather -> hi/lo output ----------------
__global__ void __launch_bounds__(256) aggregate_kernel(
    const float* __restrict__ h,
    const int*   __restrict__ off,
    const int*   __restrict__ srcs,
    bf16*        __restrict__ ahl)
{
    int node = (blockIdx.x * blockDim.x + threadIdx.x) >> 5;
    int lane = threadIdx.x & 31;
    if (node >= N_NODES) return;
    int b = __ldg(off + node);
    int e = __ldg(off + node + 1);
    float4 acc = make_float4(0.f, 0.f, 0.f, 0.f);
    int i = b;
    for (; i + 3 < e; i += 4) {
        int s0 = __ldg(srcs + i + 0);
        int s1 = __ldg(srcs + i + 1);
        int s2 = __ldg(srcs + i + 2);
        int s3 = __ldg(srcs + i + 3);
        float4 v0 = __ldg(reinterpret_cast<const float4*>(h + (size_t)s0 * 128) + lane);
        float4 v1 = __ldg(reinterpret_cast<const float4*>(h + (size_t)s1 * 128) + lane);
        float4 v2 = __ldg(reinterpret_cast<const float4*>(h + (size_t)s2 * 128) + lane);
        float4 v3 = __ldg(reinterpret_cast<const float4*>(h + (size_t)s3 * 128) + lane);
        acc.x += (v0.x + v1.x) + (v2.x + v3.x);
        acc.y += (v0.y + v1.y) + (v2.y + v3.y);
        acc.z += (v0.z + v1.z) + (v2.z + v3.z);
        acc.w += (v0.w + v1.w) + (v2.w + v3.w);
    }
    for (; i < e; ++i) {
        int s = __ldg(srcs + i);
        float4 v = __ldg(reinterpret_cast<const float4*>(h + (size_t)s * 128) + lane);
        acc.x += v.x; acc.y += v.y; acc.z += v.z; acc.w += v.w;
    }
    uint2 hi, lo;
    split4(acc, hi, lo);
    *reinterpret_cast<uint2*>(ahl + (size_t)node * 256 + lane * 4)       = hi;
    *reinterpret_cast<uint2*>(ahl + (size_t)node * 256 + 128 + lane * 4) = lo;
}

// ================ conversion-free WMMA bf16x2 SAGE GEMM ================
// CTA 128x128, 8 warps 2(m)x4(n), warp tile 64x32.
// K = 256 in 8 chunks of 32: chunks 0-3 = agg, 4-7 = h. All operands pre-split
// bf16 hi/lo; pure cp.async double-buffer -> ldmatrix -> mma.
#define A_HI 0
#define A_LO 10240
#define B_HI 20480
#define B_LO 30720
#define STAGE 40960
#define SM_TOTAL (2 * STAGE)   // 81920 -> 2 CTAs/SM

__device__ __forceinline__ void load_chunk(
    int c, uint32_t stg,
    const bf16* __restrict__ ahl, const bf16* __restrict__ hhl,
    const bf16* __restrict__ whi, const bf16* __restrict__ wlo,
    int block_row, int tid)
{
    const bf16* A = (c < 4) ? ahl : hhl;
    const int k0 = (c & 3) * 32;
    const int row = tid >> 1;         // 0..127
    const int h16 = (tid & 1) * 16;   // col offset within chunk
    const bf16* srcA = A + (size_t)(block_row + row) * 256 + k0 + h16;
    uint32_t dAh = stg + A_HI + row * 80 + h16 * 2;
    uint32_t dAl = stg + A_LO + row * 80 + h16 * 2;
    cp16(dAh,      srcA);
    cp16(dAh + 16, srcA + 8);
    cp16(dAl,      srcA + 128);
    cp16(dAl + 16, srcA + 136);
    const bf16* srcBh = whi + ((size_t)c * 128 + row) * LDT32 + h16;
    const bf16* srcBl = wlo + ((size_t)c * 128 + row) * LDT32 + h16;
    uint32_t dBh = stg + B_HI + row * 80 + h16 * 2;
    uint32_t dBl = stg + B_LO + row * 80 + h16 * 2;
    cp16(dBh,      srcBh);
    cp16(dBh + 16, srcBh + 8);
    cp16(dBl,      srcBl);
    cp16(dBl + 16, srcBl + 8);
}

__global__ void __launch_bounds__(256, 2)
sage_wmma_kernel(
    const bf16*  __restrict__ ahl,   // aggregated, hi/lo rows
    const bf16*  __restrict__ hhl,   // self features, hi/lo rows
    const bf16*  __restrict__ whi,   // layer base, chunk32-tiled
    const bf16*  __restrict__ wlo,
    const float* __restrict__ bias,
    float*       __restrict__ out,   // fp32 rows (padded)
    bf16*        __restrict__ ohl,   // hi/lo rows (padded)
    int do_relu, int write_hl)
{
    extern __shared__ char smem[];
    const uint32_t sbase = smem_u32(smem);
    const int tid = threadIdx.x;
    const int wid = tid >> 5;
    const int block_row = blockIdx.x * 128;

    const int wm = (wid & 1) * 64;
    const int wn = (wid >> 1) * 32;

    wmma::fragment<wmma::accumulator, 16, 16, 16, float> acc[4][2];
#pragma unroll
    for (int i = 0; i < 4; ++i)
#pragma unroll
        for (int j = 0; j < 2; ++j) wmma::fill_fragment(acc[i][j], 0.f);

    load_chunk(0, sbase,         ahl, hhl, whi, wlo, block_row, tid);
    CP_COMMIT();
    load_chunk(1, sbase + STAGE, ahl, hhl, whi, wlo, block_row, tid);
    CP_COMMIT();

#pragma unroll 1
    for (int c = 0; c < 8; ++c) {
        if (c < 7) CP_WAIT1(); else CP_WAIT0();
        __syncthreads();

        const char* st = smem + (c & 1) * STAGE;
        const bf16* sAhi = reinterpret_cast<const bf16*>(st + A_HI);
        const bf16* sAlo = reinterpret_cast<const bf16*>(st + A_LO);
        const bf16* sBhi = reinterpret_cast<const bf16*>(st + B_HI);
        const bf16* sBlo = reinterpret_cast<const bf16*>(st + B_LO);

#pragma unroll
        for (int ks = 0; ks < 2; ++ks) {
            wmma::fragment<wmma::matrix_a, 16, 16, 16, bf16, wmma::row_major> fah[4], fal[4];
#pragma unroll
            for (int i = 0; i < 4; ++i) {
                wmma::load_matrix_sync(fah[i], sAhi + (wm + i * 16) * LDT32 + ks * 16, LDT32);
                wmma::load_matrix_sync(fal[i], sAlo + (wm + i * 16) * LDT32 + ks * 16, LDT32);
            }
#pragma unroll
            for (int j = 0; j < 2; ++j) {
                wmma::fragment<wmma::matrix_b, 16, 16, 16, bf16, wmma::col_major> fbh, fbl;
                wmma::load_matrix_sync(fbh, sBhi + (wn + j * 16) * LDT32 + ks * 16, LDT32);
                wmma::load_matrix_sync(fbl, sBlo + (wn + j * 16) * LDT32 + ks * 16, LDT32);
#pragma unroll
                for (int i = 0; i < 4; ++i) {
                    wmma::mma_sync(acc[i][j], fah[i], fbh, acc[i][j]);
                    wmma::mma_sync(acc[i][j], fah[i], fbl, acc[i][j]);
                    wmma::mma_sync(acc[i][j], fal[i], fbh, acc[i][j]);
                }
            }
        }
        __syncthreads();
        if (c + 2 < 8) {
            load_chunk(c + 2, sbase + (c & 1) * STAGE, ahl, hhl, whi, wlo, block_row, tid);
            CP_COMMIT();
        }
    }

    // ---- epilogue: frags -> SMEM f32 (ldm 132) -> bias/relu -> fp32 + hi/lo rows ----
    float* sEpi = reinterpret_cast<float*>(smem);
#pragma unroll
    for (int i = 0; i < 4; ++i)
#pragma unroll
        for (int j = 0; j < 2; ++j)
            wmma::store_matrix_sync(sEpi + (wm + i * 16) * 132 + wn + j * 16,
                                    acc[i][j], 132, wmma::mem_row_major);
    __syncthreads();

    {
        const int row = tid >> 1;
        const int cs  = (tid & 1) * 64;
        float* orow = out + (size_t)(block_row + row) * 128 + cs;
        bf16*  hrow = ohl + (size_t)(block_row + row) * 256 + cs;
#pragma unroll
        for (int cb = 0; cb < 64; cb += 4) {
            float4 v = *reinterpret_cast<const float4*>(sEpi + row * 132 + cs + cb);
            float4 b = __ldg(reinterpret_cast<const float4*>(bias + cs + cb));
            v.x += b.x; v.y += b.y; v.z += b.z; v.w += b.w;
            if (do_relu) {
                v.x = fmaxf(v.x, 0.f); v.y = fmaxf(v.y, 0.f);
                v.z = fmaxf(v.z, 0.f); v.w = fmaxf(v.w, 0.f);
            }
            *reinterpret_cast<float4*>(orow + cb) = v;
            if (write_hl) {
                uint2 hi, lo;
                split4(v, hi, lo);
                *reinterpret_cast<uint2*>(hrow + cb)       = hi;
                *reinterpret_cast<uint2*>(hrow + 128 + cb) = lo;
            }
        }
    }
}

// ---------------- pooling ----------------
__global__ void __launch_bounds__(256) pool_kernel(
    const float* __restrict__ h,
    const int*   __restrict__ batch,
    float*       __restrict__ pooled)
{
    int node = (blockIdx.x * blockDim.x + threadIdx.x) >> 5;
    int lane = threadIdx.x & 31;
    if (node >= N_NODES) return;
    int g = __ldg(batch + node);
    float4 v = __ldg(reinterpret_cast<const float4*>(h + (size_t)node * 128) + lane);
    float* ap = pooled + (size_t)g * HIDDEN + lane * 4;
    asm volatile("red.global.add.v4.f32 [%0], {%1,%2,%3,%4};"
                 :: "l"(ap), "f"(v.x), "f"(v.y), "f"(v.z), "f"(v.w) : "memory");
}

// ---------------- output head ----------------
__global__ void out_kernel(
    const float* __restrict__ pooled,
    const float* __restrict__ Wout,
    const float* __restrict__ bout,
    float*       __restrict__ out)
{
    int idx = blockIdx.x * blockDim.x + threadIdx.x;
    if (idx >= NUM_GRAPHS * N_CLASSES) return;
    int g = idx / N_CLASSES;
    int c = idx % N_CLASSES;
    float s = __ldg(bout + c);
    const float* p = pooled + (size_t)g * HIDDEN;
    const float* w = Wout + (size_t)c * HIDDEN;
#pragma unroll 8
    for (int k = 0; k < HIDDEN; ++k) s = fmaf(p[k], w[k], s);
    out[idx] = s;
}

// ---------------- launch ----------------
extern "C" void kernel_launch(void* const* d_in, const int* in_sizes, int n_in,
                              void* d_out, int out_size)
{
    const float* x     = (const float*)d_in[0];
    const int*   ei    = (const int*)  d_in[1];
    const int*   batch = (const int*)  d_in[2];
    const float* W1l = (const float*)d_in[3];
    const float* b1  = (const float*)d_in[4];
    const float* W1r = (const float*)d_in[5];
    const float* W2l = (const float*)d_in[6];
    const float* b2  = (const float*)d_in[7];
    const float* W2r = (const float*)d_in[8];
    const float* W3l = (const float*)d_in[9];
    const float* b3  = (const float*)d_in[10];
    const float* W3r = (const float*)d_in[11];
    const float* Wout = (const float*)d_in[12];
    const float* bout = (const float*)d_in[13];
    float* out = (float*)d_out;

    float *h1, *h2, *pooled;
    bf16 *xhl, *ahl, *h1hl, *h2hl, *whi, *wlo;
    int *deg, *off, *cur, *srcs, *blksum, *blkoff;
    cudaGetSymbolAddress((void**)&h1,     g_h1);
    cudaGetSymbolAddress((void**)&h2,     g_h2);
    cudaGetSymbolAddress((void**)&xhl,    g_xhl);
    cudaGetSymbolAddress((void**)&ahl,    g_ahl);
    cudaGetSymbolAddress((void**)&h1hl,   g_h1hl);
    cudaGetSymbolAddress((void**)&h2hl,   g_h2hl);
    cudaGetSymbolAddress((void**)&whi,    g_whi);
    cudaGetSymbolAddress((void**)&wlo,    g_wlo);
    cudaGetSymbolAddress((void**)&pooled, g_pooled);
    cudaGetSymbolAddress((void**)&deg,    g_deg);
    cudaGetSymbolAddress((void**)&off,    g_off);
    cudaGetSymbolAddress((void**)&cur,    g_cur);
    cudaGetSymbolAddress((void**)&srcs,   g_srcs);
    cudaGetSymbolAddress((void**)&blksum, g_blksum);
    cudaGetSymbolAddress((void**)&blkoff, g_blkoff);

    cudaFuncSetAttribute(sage_wmma_kernel,
                         cudaFuncAttributeMaxDynamicSharedMemorySize, SM_TOTAL);

    const int edge_blocks = (N_EDGES + 255) / 256;
    const int node_blocks = NBLK;
    const int gemm_blocks = N_PAD / 128;   // 782
    const int warp_blocks = (N_NODES * 32 + 255) / 256;
    const int WSTRIDE = 8 * 128 * LDT32;   // per-layer weight stride

    // one-time conversions
    cvt_x_kernel<<<(N_NODES * 32 + 255) / 256, 256>>>(x, xhl);
    cvt_w_kernel<<<(3 * 128 * 64 + 255) / 256, 256>>>(W1l, W1r, W2l, W2r, W3l, W3r, whi, wlo);

    // CSR build
    zero_deg_kernel<<<node_blocks, 256>>>(deg);
    hist_kernel<<<edge_blocks, 256>>>(ei, deg);
    partial_kernel<<<node_blocks, 256>>>(deg, blksum);
    scan_blocks_kernel<<<1, 512>>>(blksum, blkoff);
    fill_off_kernel<<<node_blocks, 256>>>(deg, blkoff, off, cur);
    fill_kernel<<<edge_blocks, 256>>>(ei, cur, srcs);

    // layer 1: x -> h1 (+h1hl)
    aggregate_kernel<<<warp_blocks, 256>>>(x, off, srcs, ahl);
    sage_wmma_kernel<<<gemm_blocks, 256, SM_TOTAL>>>(ahl, xhl, whi, wlo, b1, h1, h1hl, 1, 1);

    // layer 2: h1 -> h2 (+h2hl)
    aggregate_kernel<<<warp_blocks, 256>>>(h1, off, srcs, ahl);
    sage_wmma_kernel<<<gemm_blocks, 256, SM_TOTAL>>>(ahl, h1hl, whi + WSTRIDE, wlo + WSTRIDE, b2, h2, h2hl, 1, 1);

    // layer 3: h2 -> h1 (fp32 only, no relu)
    aggregate_kernel<<<warp_blocks, 256>>>(h2, off, srcs, ahl);
    sage_wmma_kernel<<<gemm_blocks, 256, SM_TOTAL>>>(ahl, h2hl, whi + 2 * WSTRIDE, wlo + 2 * WSTRIDE, b3, h1, h1hl, 0, 0);

    // pool + head
    cudaMemsetAsync(pooled, 0, NUM_GRAPHS * HIDDEN * sizeof(float));
    pool_kernel<<<warp_blocks, 256>>>(h1, batch, pooled);
    out_kernel<<<(NUM_GRAPHS * N_CLASSES + 127) / 128, 128>>>(pooled, Wout, bout, out);
}